// round 15
// baseline (speedup 1.0000x reference)
#include <cuda_runtime.h>
#include <math.h>

#define N 512
#define FN 8
#define FE 1
#define E 32
#define D0 14   // 6 + FN
#define NF 8    // frames
#define JT 256  // j-tile width in k_pair
#define MS2 260 // m1T row stride (floats)

// ---------------- device scratch ----------------
__device__ float g_Vv[9];
__device__ float g_center[3];
__device__ float g_h0[NF * N * D0];
__device__ float g_pjT[NF * E * N];   // [o][l][j]
__device__ float g_pic[NF * N * E];   // pre_i + b1 folded
__device__ float g_agg[NF * N * E];
__device__ float g_h[NF * N * E];
__device__ float g_so[NF * N * 6];

// packed fp32x2 FMA (Blackwell FFMA2 via PTX)
__device__ __forceinline__ float2 fma2(float2 a, float2 b, float2 c) {
    unsigned long long au = *reinterpret_cast<unsigned long long*>(&a);
    unsigned long long bu = *reinterpret_cast<unsigned long long*>(&b);
    unsigned long long cu = *reinterpret_cast<unsigned long long*>(&c);
    unsigned long long du;
    asm("fma.rn.f32x2 %0, %1, %2, %3;" : "=l"(du) : "l"(au), "l"(bu), "l"(cu));
    return *reinterpret_cast<float2*>(&du);
}

// ---------------- setup: center, covariance, 3x3 eigh (float Jacobi) ----------------
__global__ void k_setup(const float* __restrict__ x) {
    __shared__ float red[512];
    __shared__ float cen[3];
    __shared__ float Rsh[6];
    int t = threadIdx.x;
    float xv[3];
    xv[0] = x[t * 3 + 0]; xv[1] = x[t * 3 + 1]; xv[2] = x[t * 3 + 2];
    for (int d = 0; d < 3; d++) {
        red[t] = xv[d]; __syncthreads();
        for (int s = 256; s > 0; s >>= 1) { if (t < s) red[t] += red[t + s]; __syncthreads(); }
        if (t == 0) cen[d] = red[0] * (1.0f / N);
        __syncthreads();
    }
    float xc[3] = {xv[0] - cen[0], xv[1] - cen[1], xv[2] - cen[2]};
    const int pi_[6] = {0, 0, 0, 1, 1, 2};
    const int qi_[6] = {0, 1, 2, 1, 2, 2};
    for (int e6 = 0; e6 < 6; e6++) {
        red[t] = xc[pi_[e6]] * xc[qi_[e6]]; __syncthreads();
        for (int s = 256; s > 0; s >>= 1) { if (t < s) red[t] += red[t + s]; __syncthreads(); }
        if (t == 0) Rsh[e6] = red[0];
        __syncthreads();
    }
    if (t == 0) {
        float a[3][3], V[3][3];
        a[0][0] = Rsh[0]; a[0][1] = a[1][0] = Rsh[1]; a[0][2] = a[2][0] = Rsh[2];
        a[1][1] = Rsh[3]; a[1][2] = a[2][1] = Rsh[4]; a[2][2] = Rsh[5];
        for (int i = 0; i < 3; i++) for (int j = 0; j < 3; j++) V[i][j] = (i == j) ? 1.0f : 0.0f;
        for (int sweep = 0; sweep < 12; sweep++) {
            float off = a[0][1] * a[0][1] + a[0][2] * a[0][2] + a[1][2] * a[1][2];
            float diag = a[0][0] * a[0][0] + a[1][1] * a[1][1] + a[2][2] * a[2][2];
            if (off <= 1e-14f * diag) break;
            for (int pp = 0; pp < 2; pp++) for (int qq = pp + 1; qq < 3; qq++) {
                float apq = a[pp][qq];
                if (fabsf(apq) < 1e-30f) continue;
                float theta = (a[qq][qq] - a[pp][pp]) / (2.0f * apq);
                float tt = (theta >= 0.0f ? 1.0f : -1.0f) / (fabsf(theta) + sqrtf(theta * theta + 1.0f));
                float c = rsqrtf(tt * tt + 1.0f), sn = tt * c;
                float app = a[pp][pp], aqq = a[qq][qq];
                a[pp][pp] = app - tt * apq; a[qq][qq] = aqq + tt * apq;
                a[pp][qq] = a[qq][pp] = 0.0f;
                int rr = 3 - pp - qq;
                float arp = a[rr][pp], arq = a[rr][qq];
                a[rr][pp] = a[pp][rr] = c * arp - sn * arq;
                a[rr][qq] = a[qq][rr] = sn * arp + c * arq;
                for (int r = 0; r < 3; r++) {
                    float vrp = V[r][pp], vrq = V[r][qq];
                    V[r][pp] = c * vrp - sn * vrq;
                    V[r][qq] = sn * vrp + c * vrq;
                }
            }
        }
        float w[3] = {a[0][0], a[1][1], a[2][2]};
        int idx[3] = {0, 1, 2};
        for (int i = 0; i < 2; i++) for (int j = i + 1; j < 3; j++)
            if (w[idx[j]] < w[idx[i]]) { int tmp = idx[i]; idx[i] = idx[j]; idx[j] = tmp; }
        for (int j = 0; j < 3; j++) for (int i = 0; i < 3; i++)
            g_Vv[i * 3 + j] = V[i][idx[j]];
        g_center[0] = cen[0]; g_center[1] = cen[1]; g_center[2] = cen[2];
    }
}

// ---------------- embed: warp per (frame,node), grid 512, float4 staging ----------------
__global__ void __launch_bounds__(256) k_embed(const float* __restrict__ x, const float* __restrict__ v,
                                               const float* __restrict__ nfeat,
                                               const float* __restrict__ ew1, const float* __restrict__ eb1) {
    __shared__ float s_wj[D0 * E], s_wi[D0 * E], s_b1[E];
    __shared__ float s_h0[8][16];
    int t = threadIdx.x;
    for (int idx = t; idx < D0 * E / 4; idx += 256) {
        ((float4*)s_wj)[idx] = ((const float4*)(ew1 + E))[idx];
        ((float4*)s_wi)[idx] = ((const float4*)(ew1 + E + D0 * E))[idx];
    }
    if (t < E) s_b1[t] = eb1[t];
    __syncthreads();
    int w = t >> 5, k = t & 31;
    int gid = blockIdx.x * 8 + w;
    int o = gid >> 9, n = gid & (N - 1);
    if (k < 6) {
        int i = (k < 3) ? k : (k - 3);
        float sgn = ((o >> (2 - i)) & 1) ? -1.f : 1.f;
        float s;
        if (k < 3) {
            s = (x[n * 3 + 0] - g_center[0]) * g_Vv[0 * 3 + i]
              + (x[n * 3 + 1] - g_center[1]) * g_Vv[1 * 3 + i]
              + (x[n * 3 + 2] - g_center[2]) * g_Vv[2 * 3 + i];
        } else {
            s = v[n * 3 + 0] * g_Vv[0 * 3 + i] + v[n * 3 + 1] * g_Vv[1 * 3 + i] + v[n * 3 + 2] * g_Vv[2 * 3 + i];
        }
        s_h0[w][k] = sgn * s;
    } else if (k < D0) {
        s_h0[w][k] = nfeat[n * FN + (k - 6)];
    }
    __syncwarp();
    if (k < D0) g_h0[gid * D0 + k] = s_h0[w][k];
    float pj = 0.f, pic = s_b1[k];
#pragma unroll
    for (int d = 0; d < D0; d++) {
        float h = s_h0[w][d];
        pj = fmaf(h, s_wj[d * E + k], pj);
        pic = fmaf(h, s_wi[d * E + k], pic);
    }
    g_pjT[o * E * N + k * N + n] = pj;
    g_pic[gid * E + k] = pic;
}

// ---------------- pair loop: R14 geometry, W2 pre-duplicated in smem (frees 64 regs) ----------------
// grid (128, 8), block 256. 8 phases. Dynamic smem: double-buffered m1T.
__global__ void __launch_bounds__(256, 2) k_pair(const float* __restrict__ edge,
                                                 const float* __restrict__ ew1,
                                                 const float* __restrict__ ew2,
                                                 const float* __restrict__ eb2,
                                                 const float* __restrict__ pjT_in,
                                                 const float* __restrict__ pic_in) {
    extern __shared__ __align__(16) float dyn[];
    float* bufA = dyn;
    float* bufB = dyn + E * MS2;
    __shared__ float2 s_wp[4][E];          // (we, pic) per i-row
    __shared__ __align__(16) float s_w2d[E * E * 2];  // [l][(w_k,w_k) duplicated pairs]
    __shared__ float s_red[4][16][E];      // per-i partials
    int o = blockIdx.y, i0 = blockIdx.x * 4;
    int t = threadIdx.x;
    if (t < 128) {
        int ii = t >> 5, l = t & 31;
        s_wp[ii][l] = make_float2(__ldg(ew1 + l), pic_in[(o * N + i0 + ii) * E + l]);
    }
    // stage W2 duplicated: s_w2d[l*64 + 2k] = s_w2d[l*64 + 2k + 1] = W2[l][k]
    for (int idx = t; idx < E * E; idx += 256) {
        float w = __ldg(ew2 + idx);
        int l = idx >> 5, k = idx & 31;
        s_w2d[l * 64 + 2 * k] = w;
        s_w2d[l * 64 + 2 * k + 1] = w;
    }
    // consumer roles
    int kg = t & 15, jg = t >> 4;
    int k0 = kg * 2;
    float b2a = __ldg(eb2 + k0), b2b = __ldg(eb2 + k0 + 1);
    // builder roles
    int jq = t & 63, lb = t >> 6;
    const float* pjTo = pjT_in + o * (E * N);
    __syncthreads();

    auto build = [&](float* dst, int ii, int jt) {
        float4 ev = *(const float4*)(edge + (i0 + ii) * N + jt * JT + jq * 4);
#pragma unroll
        for (int q = 0; q < 8; q++) {
            int l = lb * 8 + q;
            float2 wp = s_wp[ii][l];
            float4 pj = *(const float4*)(pjTo + l * N + jt * JT + jq * 4);
            float4 m;
            m.x = fmaxf(fmaf(ev.x, wp.x, pj.x + wp.y), 0.f);
            m.y = fmaxf(fmaf(ev.y, wp.x, pj.y + wp.y), 0.f);
            m.z = fmaxf(fmaf(ev.z, wp.x, pj.z + wp.y), 0.f);
            m.w = fmaxf(fmaf(ev.w, wp.x, pj.w + wp.y), 0.f);
            *(float4*)(dst + l * MS2 + jq * 4) = m;
        }
    };

    float sa = 0.f, sb = 0.f;

    auto consume = [&](const float* tile) {
        float2 acc[8][2];
#pragma unroll
        for (int p = 0; p < 8; p++) { acc[p][0] = make_float2(0.f, 0.f); acc[p][1] = make_float2(0.f, 0.f); }
#pragma unroll
        for (int l = 0; l < E; l++) {
            const float* row = tile + l * MS2 + jg * 16;
            float4 r0 = *(const float4*)(row);
            float4 r1 = *(const float4*)(row + 4);
            float4 r2 = *(const float4*)(row + 8);
            float4 r3 = *(const float4*)(row + 12);
            float4 wv = *(const float4*)(s_w2d + l * 64 + kg * 4);  // (wa,wa,wb,wb)
            float2 wda = make_float2(wv.x, wv.y);
            float2 wdb = make_float2(wv.z, wv.w);
            float2 av[8];
            av[0] = make_float2(r0.x, r0.y); av[1] = make_float2(r0.z, r0.w);
            av[2] = make_float2(r1.x, r1.y); av[3] = make_float2(r1.z, r1.w);
            av[4] = make_float2(r2.x, r2.y); av[5] = make_float2(r2.z, r2.w);
            av[6] = make_float2(r3.x, r3.y); av[7] = make_float2(r3.z, r3.w);
#pragma unroll
            for (int p = 0; p < 8; p++) {
                acc[p][0] = fma2(av[p], wda, acc[p][0]);
                acc[p][1] = fma2(av[p], wdb, acc[p][1]);
            }
        }
#pragma unroll
        for (int p = 0; p < 8; p++) {
            sa += fmaxf(acc[p][0].x + b2a, 0.f) + fmaxf(acc[p][0].y + b2a, 0.f);
            sb += fmaxf(acc[p][1].x + b2b, 0.f) + fmaxf(acc[p][1].y + b2b, 0.f);
        }
    };

    build(bufA, 0, 0);
    __syncthreads();
#pragma unroll
    for (int p = 0; p < 8; p++) {
        int jt = p & 1;
        if (p < 7) build((p & 1) ? bufA : bufB, (p + 1) >> 1, (p + 1) & 1);
        consume((p & 1) ? bufB : bufA);
        if (jt == 1) {
            *(float2*)(&s_red[p >> 1][jg][k0]) = make_float2(sa, sb);
            sa = 0.f; sb = 0.f;
        }
        __syncthreads();
    }
    if (t < 128) {
        int ii = t >> 5, k = t & 31;
        float s = 0.f;
#pragma unroll
        for (int g = 0; g < 16; g++) s += s_red[ii][g][k];
        g_agg[(o * N + i0 + ii) * E + k] = s;
    }
}

// ---------------- node update layer 0: warp per gid, float4 staging ----------------
__global__ void __launch_bounds__(256) k_node0(const float* __restrict__ nw1, const float* __restrict__ nb1,
                                               const float* __restrict__ nw2, const float* __restrict__ nb2,
                                               const float* __restrict__ e1w1, const float* __restrict__ e1b1) {
    __shared__ float s_nw1[(D0 + E) * E];
    __shared__ float s_nw2[E * E];
    __shared__ float s_ewj[E * E], s_ewi[E * E];
    __shared__ float s_nb1[E], s_nb2[E], s_eb1[E];
    __shared__ float s_a[8][16], s_b[8][32], s_c[8][32];
    int t = threadIdx.x;
    for (int idx = t; idx < (D0 + E) * E / 4; idx += 256) ((float4*)s_nw1)[idx] = ((const float4*)nw1)[idx];
    for (int idx = t; idx < E * E / 4; idx += 256) {
        ((float4*)s_nw2)[idx] = ((const float4*)nw2)[idx];
        ((float4*)s_ewj)[idx] = ((const float4*)(e1w1 + E))[idx];
        ((float4*)s_ewi)[idx] = ((const float4*)(e1w1 + E + E * E))[idx];
    }
    if (t < E) { s_nb1[t] = nb1[t]; s_nb2[t] = nb2[t]; s_eb1[t] = e1b1[t]; }
    __syncthreads();
    int w = t >> 5, k = t & 31;
    int gid = blockIdx.x * 8 + w;
    int o = gid >> 9, n = gid & (N - 1);
    if (k < D0) s_a[w][k] = g_h0[gid * D0 + k];
    s_b[w][k] = g_agg[gid * E + k];
    __syncwarp();
    float dn = s_nb1[k];
#pragma unroll
    for (int d = 0; d < D0; d++) dn = fmaf(s_a[w][d], s_nw1[d * E + k], dn);
#pragma unroll
    for (int d = 0; d < E; d++) dn = fmaf(s_b[w][d], s_nw1[(D0 + d) * E + k], dn);
    dn = fmaxf(dn, 0.f);
    s_c[w][k] = dn;
    __syncwarp();
    float h1 = s_nb2[k];
#pragma unroll
    for (int l = 0; l < E; l++) h1 = fmaf(s_c[w][l], s_nw2[l * E + k], h1);
    g_h[gid * E + k] = h1;
    __syncwarp();
    s_c[w][k] = h1;
    __syncwarp();
    float pj = 0.f, pic = s_eb1[k];
#pragma unroll
    for (int d = 0; d < E; d++) {
        float h = s_c[w][d];
        pj = fmaf(h, s_ewj[d * E + k], pj);
        pic = fmaf(h, s_ewi[d * E + k], pic);
    }
    g_pjT[o * E * N + k * N + n] = pj;
    g_pic[gid * E + k] = pic;
}

// ---------------- node update layer 1 + decoder: warp per gid, float4 staging ----------------
__global__ void __launch_bounds__(256) k_node1(const float* __restrict__ nw1, const float* __restrict__ nb1,
                                               const float* __restrict__ nw2, const float* __restrict__ nb2,
                                               const float* __restrict__ dw1, const float* __restrict__ db1,
                                               const float* __restrict__ dw2, const float* __restrict__ db2) {
    __shared__ float s_nw1[2 * E * E];
    __shared__ float s_nw2[E * E];
    __shared__ float s_dw1[E * E];
    __shared__ float s_dw2[E * 6];
    __shared__ float s_nb1[E], s_nb2[E], s_db1[E], s_db2[6];
    __shared__ float s_a[8][32], s_b[8][32], s_c[8][32];
    int t = threadIdx.x;
    for (int idx = t; idx < 2 * E * E / 4; idx += 256) ((float4*)s_nw1)[idx] = ((const float4*)nw1)[idx];
    for (int idx = t; idx < E * E / 4; idx += 256) {
        ((float4*)s_nw2)[idx] = ((const float4*)nw2)[idx];
        ((float4*)s_dw1)[idx] = ((const float4*)dw1)[idx];
    }
    for (int idx = t; idx < E * 6 / 4; idx += 256) ((float4*)s_dw2)[idx] = ((const float4*)dw2)[idx];
    if (t < E) { s_nb1[t] = nb1[t]; s_nb2[t] = nb2[t]; s_db1[t] = db1[t]; }
    if (t < 6) s_db2[t] = db2[t];
    __syncthreads();
    int w = t >> 5, k = t & 31;
    int gid = blockIdx.x * 8 + w;
    s_a[w][k] = g_h[gid * E + k];
    s_b[w][k] = g_agg[gid * E + k];
    __syncwarp();
    float dn = s_nb1[k];
#pragma unroll
    for (int d = 0; d < E; d++) dn = fmaf(s_a[w][d], s_nw1[d * E + k], dn);
#pragma unroll
    for (int d = 0; d < E; d++) dn = fmaf(s_b[w][d], s_nw1[(E + d) * E + k], dn);
    dn = fmaxf(dn, 0.f);
    s_c[w][k] = dn;
    __syncwarp();
    float h2 = s_nb2[k];
#pragma unroll
    for (int l = 0; l < E; l++) h2 = fmaf(s_c[w][l], s_nw2[l * E + k], h2);
    g_h[gid * E + k] = h2;
    __syncwarp();
    s_a[w][k] = fmaxf(h2, 0.f);
    __syncwarp();
    float sd = s_db1[k];
#pragma unroll
    for (int l = 0; l < E; l++) sd = fmaf(s_a[w][l], s_dw1[l * E + k], sd);
    sd = fmaxf(sd, 0.f);
    s_b[w][k] = sd;
    __syncwarp();
    if (k < 6) {
        float s = s_db2[k];
#pragma unroll
        for (int l = 0; l < E; l++) s = fmaf(s_b[w][l], s_dw2[l * 6 + k], s);
        g_so[gid * 6 + k] = s;
    }
}

// ---------------- final: h_mean, coef, frame inversion, outputs + edge copy ----------------
__global__ void k_final(const float* __restrict__ x, const float* __restrict__ v,
                        const float* __restrict__ vw1, const float* __restrict__ vb1,
                        const float* __restrict__ vw2, const float* __restrict__ vb2,
                        const float4* __restrict__ edge4,
                        float* __restrict__ out) {
    if (blockIdx.x >= 2) {
        int b = blockIdx.x - 2;
        float4* dst = (float4*)(out + E * N);
        int base = b * 1024 + threadIdx.x;
#pragma unroll
        for (int q = 0; q < 4; q++) dst[base + q * 256] = edge4[base + q * 256];
        return;
    }
    __shared__ float s_w1[E * E], s_b1[E], s_w2[E];
    __shared__ float s_b2;
    __shared__ float s_Vv[9];
    int t = threadIdx.x;
    for (int i = t; i < E * E; i += blockDim.x) s_w1[i] = vw1[i];
    if (t < E) { s_b1[t] = vb1[t]; s_w2[t] = vw2[t]; }
    if (t == 0) s_b2 = vb2[0];
    if (t < 9) s_Vv[t] = g_Vv[t];
    __syncthreads();
    int n = blockIdx.x * 256 + t;
    float hm[E];
#pragma unroll
    for (int k = 0; k < E; k++) {
        float s = 0.f;
#pragma unroll
        for (int o = 0; o < NF; o++) s += g_h[(o * N + n) * E + k];
        hm[k] = s * 0.125f;
        out[n * E + k] = hm[k];
    }
    float u[E];
#pragma unroll
    for (int k = 0; k < E; k++) {
        float s = s_b1[k];
#pragma unroll
        for (int l = 0; l < E; l++) s = fmaf(fmaxf(hm[l], 0.f), s_w1[l * E + k], s);
        u[k] = fmaxf(s, 0.f);
    }
    float coef = s_b2;
#pragma unroll
    for (int l = 0; l < E; l++) coef = fmaf(u[l], s_w2[l], coef);
    float Sx[3] = {0.f, 0.f, 0.f}, Sv[3] = {0.f, 0.f, 0.f};
#pragma unroll
    for (int o = 0; o < NF; o++) {
#pragma unroll
        for (int jj = 0; jj < 3; jj++) {
            float sgn = ((o >> (2 - jj)) & 1) ? -1.f : 1.f;
            Sx[jj] += sgn * g_so[(o * N + n) * 6 + jj];
            Sv[jj] += sgn * g_so[(o * N + n) * 6 + 3 + jj];
        }
    }
#pragma unroll
    for (int i = 0; i < 3; i++) {
        float dx = 0.125f * (s_Vv[i * 3 + 0] * Sx[0] + s_Vv[i * 3 + 1] * Sx[1] + s_Vv[i * 3 + 2] * Sx[2]);
        float dv = 0.125f * (s_Vv[i * 3 + 0] * Sv[0] + s_Vv[i * 3 + 1] * Sv[1] + s_Vv[i * 3 + 2] * Sv[2]);
        float vo = v[n * 3 + i] + dv;
        float xo = fmaf(vo, coef, x[n * 3 + i] + dx);
        out[E * N + N * N + n * 3 + i] = xo;
        out[E * N + N * N + 3 * N + n * 3 + i] = vo;
    }
}

extern "C" void kernel_launch(void* const* d_in, const int* in_sizes, int n_in,
                              void* d_out, int out_size) {
    const float* node_feat = (const float*)d_in[0];
    const float* edge = (const float*)d_in[1];
    const float* x = (const float*)d_in[2];
    const float* v = (const float*)d_in[3];
    const float* e0w1 = (const float*)d_in[4];
    const float* e0b1 = (const float*)d_in[5];
    const float* e0w2 = (const float*)d_in[6];
    const float* e0b2 = (const float*)d_in[7];
    const float* n0w1 = (const float*)d_in[8];
    const float* n0b1 = (const float*)d_in[9];
    const float* n0w2 = (const float*)d_in[10];
    const float* n0b2 = (const float*)d_in[11];
    const float* e1w1 = (const float*)d_in[12];
    const float* e1b1 = (const float*)d_in[13];
    const float* e1w2 = (const float*)d_in[14];
    const float* e1b2 = (const float*)d_in[15];
    const float* n1w1 = (const float*)d_in[16];
    const float* n1b1 = (const float*)d_in[17];
    const float* n1w2 = (const float*)d_in[18];
    const float* n1b2 = (const float*)d_in[19];
    const float* dw1 = (const float*)d_in[20];
    const float* db1 = (const float*)d_in[21];
    const float* dw2 = (const float*)d_in[22];
    const float* db2 = (const float*)d_in[23];
    const float* vcw1 = (const float*)d_in[24];
    const float* vcb1 = (const float*)d_in[25];
    const float* vcw2 = (const float*)d_in[26];
    const float* vcb2 = (const float*)d_in[27];
    float* out = (float*)d_out;

    float* pjT; cudaGetSymbolAddress((void**)&pjT, g_pjT);
    float* pic; cudaGetSymbolAddress((void**)&pic, g_pic);

    const int dyn = 2 * E * MS2 * (int)sizeof(float);   // 66560 B
    cudaFuncSetAttribute(k_pair, cudaFuncAttributeMaxDynamicSharedMemorySize, dyn);

    k_setup<<<1, 512>>>(x);
    k_embed<<<NF * N / 8, 256>>>(x, v, node_feat, e0w1, e0b1);
    k_pair<<<dim3(N / 4, NF), 256, dyn>>>(edge, e0w1, e0w2, e0b2, pjT, pic);
    k_node0<<<NF * N / 8, 256>>>(n0w1, n0b1, n0w2, n0b2, e1w1, e1b1);
    k_pair<<<dim3(N / 4, NF), 256, dyn>>>(edge, e1w1, e1w2, e1b2, pjT, pic);
    k_node1<<<NF * N / 8, 256>>>(n1w1, n1b1, n1w2, n1b2, dw1, db1, dw2, db2);
    k_final<<<66, 256>>>(x, v, vcw1, vcb1, vcw2, vcb2, (const float4*)edge, out);
}

// round 16
// speedup vs baseline: 1.1305x; 1.1305x over previous
#include <cuda_runtime.h>
#include <math.h>

#define N 512
#define FN 8
#define FE 1
#define E 32
#define D0 14   // 6 + FN
#define NF 8    // frames
#define JT 256  // j-tile width in k_pair
#define MS2 260 // m1T row stride (floats)

// ---------------- device scratch ----------------
__device__ float g_Vv[9];
__device__ float g_center[3];
__device__ float g_h0[NF * N * D0];
__device__ float g_pjT[NF * E * N];   // [o][l][j]
__device__ float g_pic[NF * N * E];   // pre_i + b1 folded
__device__ float g_agg[NF * N * E];
__device__ float g_h[NF * N * E];
__device__ float g_so[NF * N * 6];

// packed fp32x2 FMA (Blackwell FFMA2 via PTX)
__device__ __forceinline__ float2 fma2(float2 a, float2 b, float2 c) {
    unsigned long long au = *reinterpret_cast<unsigned long long*>(&a);
    unsigned long long bu = *reinterpret_cast<unsigned long long*>(&b);
    unsigned long long cu = *reinterpret_cast<unsigned long long*>(&c);
    unsigned long long du;
    asm("fma.rn.f32x2 %0, %1, %2, %3;" : "=l"(du) : "l"(au), "l"(bu), "l"(cu));
    return *reinterpret_cast<float2*>(&du);
}
__device__ __forceinline__ float2 pack2(float w) {
    unsigned long long u;
    asm("mov.b64 %0, {%1, %1};" : "=l"(u) : "f"(w));
    return *reinterpret_cast<float2*>(&u);
}

// ---------------- setup: center, covariance, 3x3 eigh (float Jacobi) ----------------
__global__ void k_setup(const float* __restrict__ x) {
    __shared__ float red[512];
    __shared__ float cen[3];
    __shared__ float Rsh[6];
    int t = threadIdx.x;
    float xv[3];
    xv[0] = x[t * 3 + 0]; xv[1] = x[t * 3 + 1]; xv[2] = x[t * 3 + 2];
    for (int d = 0; d < 3; d++) {
        red[t] = xv[d]; __syncthreads();
        for (int s = 256; s > 0; s >>= 1) { if (t < s) red[t] += red[t + s]; __syncthreads(); }
        if (t == 0) cen[d] = red[0] * (1.0f / N);
        __syncthreads();
    }
    float xc[3] = {xv[0] - cen[0], xv[1] - cen[1], xv[2] - cen[2]};
    const int pi_[6] = {0, 0, 0, 1, 1, 2};
    const int qi_[6] = {0, 1, 2, 1, 2, 2};
    for (int e6 = 0; e6 < 6; e6++) {
        red[t] = xc[pi_[e6]] * xc[qi_[e6]]; __syncthreads();
        for (int s = 256; s > 0; s >>= 1) { if (t < s) red[t] += red[t + s]; __syncthreads(); }
        if (t == 0) Rsh[e6] = red[0];
        __syncthreads();
    }
    if (t == 0) {
        float a[3][3], V[3][3];
        a[0][0] = Rsh[0]; a[0][1] = a[1][0] = Rsh[1]; a[0][2] = a[2][0] = Rsh[2];
        a[1][1] = Rsh[3]; a[1][2] = a[2][1] = Rsh[4]; a[2][2] = Rsh[5];
        for (int i = 0; i < 3; i++) for (int j = 0; j < 3; j++) V[i][j] = (i == j) ? 1.0f : 0.0f;
        for (int sweep = 0; sweep < 12; sweep++) {
            float off = a[0][1] * a[0][1] + a[0][2] * a[0][2] + a[1][2] * a[1][2];
            float diag = a[0][0] * a[0][0] + a[1][1] * a[1][1] + a[2][2] * a[2][2];
            if (off <= 1e-14f * diag) break;
            for (int pp = 0; pp < 2; pp++) for (int qq = pp + 1; qq < 3; qq++) {
                float apq = a[pp][qq];
                if (fabsf(apq) < 1e-30f) continue;
                float theta = (a[qq][qq] - a[pp][pp]) / (2.0f * apq);
                float tt = (theta >= 0.0f ? 1.0f : -1.0f) / (fabsf(theta) + sqrtf(theta * theta + 1.0f));
                float c = rsqrtf(tt * tt + 1.0f), sn = tt * c;
                float app = a[pp][pp], aqq = a[qq][qq];
                a[pp][pp] = app - tt * apq; a[qq][qq] = aqq + tt * apq;
                a[pp][qq] = a[qq][pp] = 0.0f;
                int rr = 3 - pp - qq;
                float arp = a[rr][pp], arq = a[rr][qq];
                a[rr][pp] = a[pp][rr] = c * arp - sn * arq;
                a[rr][qq] = a[qq][rr] = sn * arp + c * arq;
                for (int r = 0; r < 3; r++) {
                    float vrp = V[r][pp], vrq = V[r][qq];
                    V[r][pp] = c * vrp - sn * vrq;
                    V[r][qq] = sn * vrp + c * vrq;
                }
            }
        }
        float w[3] = {a[0][0], a[1][1], a[2][2]};
        int idx[3] = {0, 1, 2};
        for (int i = 0; i < 2; i++) for (int j = i + 1; j < 3; j++)
            if (w[idx[j]] < w[idx[i]]) { int tmp = idx[i]; idx[i] = idx[j]; idx[j] = tmp; }
        for (int j = 0; j < 3; j++) for (int i = 0; i < 3; i++)
            g_Vv[i * 3 + j] = V[i][idx[j]];
        g_center[0] = cen[0]; g_center[1] = cen[1]; g_center[2] = cen[2];
    }
}

// ---------------- embed: warp per (frame,node), grid 512, float4 staging ----------------
__global__ void __launch_bounds__(256) k_embed(const float* __restrict__ x, const float* __restrict__ v,
                                               const float* __restrict__ nfeat,
                                               const float* __restrict__ ew1, const float* __restrict__ eb1) {
    __shared__ float s_wj[D0 * E], s_wi[D0 * E], s_b1[E];
    __shared__ float s_h0[8][16];
    int t = threadIdx.x;
    for (int idx = t; idx < D0 * E / 4; idx += 256) {
        ((float4*)s_wj)[idx] = ((const float4*)(ew1 + E))[idx];
        ((float4*)s_wi)[idx] = ((const float4*)(ew1 + E + D0 * E))[idx];
    }
    if (t < E) s_b1[t] = eb1[t];
    __syncthreads();
    int w = t >> 5, k = t & 31;
    int gid = blockIdx.x * 8 + w;
    int o = gid >> 9, n = gid & (N - 1);
    if (k < 6) {
        int i = (k < 3) ? k : (k - 3);
        float sgn = ((o >> (2 - i)) & 1) ? -1.f : 1.f;
        float s;
        if (k < 3) {
            s = (x[n * 3 + 0] - g_center[0]) * g_Vv[0 * 3 + i]
              + (x[n * 3 + 1] - g_center[1]) * g_Vv[1 * 3 + i]
              + (x[n * 3 + 2] - g_center[2]) * g_Vv[2 * 3 + i];
        } else {
            s = v[n * 3 + 0] * g_Vv[0 * 3 + i] + v[n * 3 + 1] * g_Vv[1 * 3 + i] + v[n * 3 + 2] * g_Vv[2 * 3 + i];
        }
        s_h0[w][k] = sgn * s;
    } else if (k < D0) {
        s_h0[w][k] = nfeat[n * FN + (k - 6)];
    }
    __syncwarp();
    if (k < D0) g_h0[gid * D0 + k] = s_h0[w][k];
    float pj = 0.f, pic = s_b1[k];
#pragma unroll
    for (int d = 0; d < D0; d++) {
        float h = s_h0[w][d];
        pj = fmaf(h, s_wj[d * E + k], pj);
        pic = fmaf(h, s_wi[d * E + k], pic);
    }
    g_pjT[o * E * N + k * N + n] = pj;
    g_pic[gid * E + k] = pic;
}

// ---------------- pair loop: R14 design, phase loop NOT unrolled (I$ fit) ----------------
// grid (128, 8), block 256. 8 phases. Dynamic smem: double-buffered m1T.
__global__ void __launch_bounds__(256, 2) k_pair(const float* __restrict__ edge,
                                                 const float* __restrict__ ew1,
                                                 const float* __restrict__ ew2,
                                                 const float* __restrict__ eb2,
                                                 const float* __restrict__ pjT_in,
                                                 const float* __restrict__ pic_in) {
    extern __shared__ __align__(16) float dyn[];
    float* bufA = dyn;
    float* bufB = dyn + E * MS2;
    __shared__ float2 s_wp[4][E];          // (we, pic) per i-row
    __shared__ __align__(16) float s_w2[E * E];
    __shared__ float s_red[4][16][E];      // per-i partials
    int o = blockIdx.y, i0 = blockIdx.x * 4;
    int t = threadIdx.x;
    if (t < 128) {
        int ii = t >> 5, l = t & 31;
        s_wp[ii][l] = make_float2(__ldg(ew1 + l), pic_in[(o * N + i0 + ii) * E + l]);
    }
    // stage W2 via one LDG.128 per thread
    ((float4*)s_w2)[t] = ((const float4*)ew2)[t];
    // consumer roles
    int kg = t & 15, jg = t >> 4;
    int k0 = kg * 2;
    float b2a = __ldg(eb2 + k0), b2b = __ldg(eb2 + k0 + 1);
    // builder roles
    int jq = t & 63, lb = t >> 6;
    const float* pjTo = pjT_in + o * (E * N);
    __syncthreads();
    // per-thread W2 registers from smem (cheap LDS.64, 16-distinct-address pattern)
    float w2a[32], w2b[32];
#pragma unroll
    for (int l = 0; l < 32; l++) {
        float2 wv = *(const float2*)(s_w2 + l * E + k0);
        w2a[l] = wv.x; w2b[l] = wv.y;
    }

    auto build = [&](float* dst, int ii, int jt) {
        float4 ev = *(const float4*)(edge + (i0 + ii) * N + jt * JT + jq * 4);
#pragma unroll
        for (int q = 0; q < 8; q++) {
            int l = lb * 8 + q;
            float2 wp = s_wp[ii][l];
            float4 pj = *(const float4*)(pjTo + l * N + jt * JT + jq * 4);
            float4 m;
            m.x = fmaxf(fmaf(ev.x, wp.x, pj.x + wp.y), 0.f);
            m.y = fmaxf(fmaf(ev.y, wp.x, pj.y + wp.y), 0.f);
            m.z = fmaxf(fmaf(ev.z, wp.x, pj.z + wp.y), 0.f);
            m.w = fmaxf(fmaf(ev.w, wp.x, pj.w + wp.y), 0.f);
            *(float4*)(dst + l * MS2 + jq * 4) = m;
        }
    };

    float sa = 0.f, sb = 0.f;

    auto consume = [&](const float* tile) {
        float2 acc[8][2];
#pragma unroll
        for (int p = 0; p < 8; p++) { acc[p][0] = make_float2(0.f, 0.f); acc[p][1] = make_float2(0.f, 0.f); }
#pragma unroll
        for (int l = 0; l < E; l++) {
            const float* row = tile + l * MS2 + jg * 16;
            float4 r0 = *(const float4*)(row);
            float4 r1 = *(const float4*)(row + 4);
            float4 r2 = *(const float4*)(row + 8);
            float4 r3 = *(const float4*)(row + 12);
            float2 wda = pack2(w2a[l]);
            float2 wdb = pack2(w2b[l]);
            float2 av[8];
            av[0] = make_float2(r0.x, r0.y); av[1] = make_float2(r0.z, r0.w);
            av[2] = make_float2(r1.x, r1.y); av[3] = make_float2(r1.z, r1.w);
            av[4] = make_float2(r2.x, r2.y); av[5] = make_float2(r2.z, r2.w);
            av[6] = make_float2(r3.x, r3.y); av[7] = make_float2(r3.z, r3.w);
#pragma unroll
            for (int p = 0; p < 8; p++) {
                acc[p][0] = fma2(av[p], wda, acc[p][0]);
                acc[p][1] = fma2(av[p], wdb, acc[p][1]);
            }
        }
#pragma unroll
        for (int p = 0; p < 8; p++) {
            sa += fmaxf(acc[p][0].x + b2a, 0.f) + fmaxf(acc[p][0].y + b2a, 0.f);
            sb += fmaxf(acc[p][1].x + b2b, 0.f) + fmaxf(acc[p][1].y + b2b, 0.f);
        }
    };

    build(bufA, 0, 0);
    __syncthreads();
    float* cur = bufA;
    float* nxt = bufB;
#pragma unroll 1
    for (int p = 0; p < 8; p++) {
        if (p < 7) build(nxt, (p + 1) >> 1, (p + 1) & 1);
        consume(cur);
        if (p & 1) {
            *(float2*)(&s_red[p >> 1][jg][k0]) = make_float2(sa, sb);
            sa = 0.f; sb = 0.f;
        }
        float* tmp = cur; cur = nxt; nxt = tmp;
        __syncthreads();
    }
    if (t < 128) {
        int ii = t >> 5, k = t & 31;
        float s = 0.f;
#pragma unroll
        for (int g = 0; g < 16; g++) s += s_red[ii][g][k];
        g_agg[(o * N + i0 + ii) * E + k] = s;
    }
}

// ---------------- node update layer 0: warp per gid, float4 staging ----------------
__global__ void __launch_bounds__(256) k_node0(const float* __restrict__ nw1, const float* __restrict__ nb1,
                                               const float* __restrict__ nw2, const float* __restrict__ nb2,
                                               const float* __restrict__ e1w1, const float* __restrict__ e1b1) {
    __shared__ float s_nw1[(D0 + E) * E];
    __shared__ float s_nw2[E * E];
    __shared__ float s_ewj[E * E], s_ewi[E * E];
    __shared__ float s_nb1[E], s_nb2[E], s_eb1[E];
    __shared__ float s_a[8][16], s_b[8][32], s_c[8][32];
    int t = threadIdx.x;
    for (int idx = t; idx < (D0 + E) * E / 4; idx += 256) ((float4*)s_nw1)[idx] = ((const float4*)nw1)[idx];
    for (int idx = t; idx < E * E / 4; idx += 256) {
        ((float4*)s_nw2)[idx] = ((const float4*)nw2)[idx];
        ((float4*)s_ewj)[idx] = ((const float4*)(e1w1 + E))[idx];
        ((float4*)s_ewi)[idx] = ((const float4*)(e1w1 + E + E * E))[idx];
    }
    if (t < E) { s_nb1[t] = nb1[t]; s_nb2[t] = nb2[t]; s_eb1[t] = e1b1[t]; }
    __syncthreads();
    int w = t >> 5, k = t & 31;
    int gid = blockIdx.x * 8 + w;
    int o = gid >> 9, n = gid & (N - 1);
    if (k < D0) s_a[w][k] = g_h0[gid * D0 + k];
    s_b[w][k] = g_agg[gid * E + k];
    __syncwarp();
    float dn = s_nb1[k];
#pragma unroll
    for (int d = 0; d < D0; d++) dn = fmaf(s_a[w][d], s_nw1[d * E + k], dn);
#pragma unroll
    for (int d = 0; d < E; d++) dn = fmaf(s_b[w][d], s_nw1[(D0 + d) * E + k], dn);
    dn = fmaxf(dn, 0.f);
    s_c[w][k] = dn;
    __syncwarp();
    float h1 = s_nb2[k];
#pragma unroll
    for (int l = 0; l < E; l++) h1 = fmaf(s_c[w][l], s_nw2[l * E + k], h1);
    g_h[gid * E + k] = h1;
    __syncwarp();
    s_c[w][k] = h1;
    __syncwarp();
    float pj = 0.f, pic = s_eb1[k];
#pragma unroll
    for (int d = 0; d < E; d++) {
        float h = s_c[w][d];
        pj = fmaf(h, s_ewj[d * E + k], pj);
        pic = fmaf(h, s_ewi[d * E + k], pic);
    }
    g_pjT[o * E * N + k * N + n] = pj;
    g_pic[gid * E + k] = pic;
}

// ---------------- node update layer 1 + decoder: warp per gid, float4 staging ----------------
__global__ void __launch_bounds__(256) k_node1(const float* __restrict__ nw1, const float* __restrict__ nb1,
                                               const float* __restrict__ nw2, const float* __restrict__ nb2,
                                               const float* __restrict__ dw1, const float* __restrict__ db1,
                                               const float* __restrict__ dw2, const float* __restrict__ db2) {
    __shared__ float s_nw1[2 * E * E];
    __shared__ float s_nw2[E * E];
    __shared__ float s_dw1[E * E];
    __shared__ float s_dw2[E * 6];
    __shared__ float s_nb1[E], s_nb2[E], s_db1[E], s_db2[6];
    __shared__ float s_a[8][32], s_b[8][32], s_c[8][32];
    int t = threadIdx.x;
    for (int idx = t; idx < 2 * E * E / 4; idx += 256) ((float4*)s_nw1)[idx] = ((const float4*)nw1)[idx];
    for (int idx = t; idx < E * E / 4; idx += 256) {
        ((float4*)s_nw2)[idx] = ((const float4*)nw2)[idx];
        ((float4*)s_dw1)[idx] = ((const float4*)dw1)[idx];
    }
    for (int idx = t; idx < E * 6 / 4; idx += 256) ((float4*)s_dw2)[idx] = ((const float4*)dw2)[idx];
    if (t < E) { s_nb1[t] = nb1[t]; s_nb2[t] = nb2[t]; s_db1[t] = db1[t]; }
    if (t < 6) s_db2[t] = db2[t];
    __syncthreads();
    int w = t >> 5, k = t & 31;
    int gid = blockIdx.x * 8 + w;
    s_a[w][k] = g_h[gid * E + k];
    s_b[w][k] = g_agg[gid * E + k];
    __syncwarp();
    float dn = s_nb1[k];
#pragma unroll
    for (int d = 0; d < E; d++) dn = fmaf(s_a[w][d], s_nw1[d * E + k], dn);
#pragma unroll
    for (int d = 0; d < E; d++) dn = fmaf(s_b[w][d], s_nw1[(E + d) * E + k], dn);
    dn = fmaxf(dn, 0.f);
    s_c[w][k] = dn;
    __syncwarp();
    float h2 = s_nb2[k];
#pragma unroll
    for (int l = 0; l < E; l++) h2 = fmaf(s_c[w][l], s_nw2[l * E + k], h2);
    g_h[gid * E + k] = h2;
    __syncwarp();
    s_a[w][k] = fmaxf(h2, 0.f);
    __syncwarp();
    float sd = s_db1[k];
#pragma unroll
    for (int l = 0; l < E; l++) sd = fmaf(s_a[w][l], s_dw1[l * E + k], sd);
    sd = fmaxf(sd, 0.f);
    s_b[w][k] = sd;
    __syncwarp();
    if (k < 6) {
        float s = s_db2[k];
#pragma unroll
        for (int l = 0; l < E; l++) s = fmaf(s_b[w][l], s_dw2[l * 6 + k], s);
        g_so[gid * 6 + k] = s;
    }
}

// ---------------- final: h_mean, coef, frame inversion, outputs + edge copy ----------------
__global__ void k_final(const float* __restrict__ x, const float* __restrict__ v,
                        const float* __restrict__ vw1, const float* __restrict__ vb1,
                        const float* __restrict__ vw2, const float* __restrict__ vb2,
                        const float4* __restrict__ edge4,
                        float* __restrict__ out) {
    if (blockIdx.x >= 2) {
        int b = blockIdx.x - 2;
        float4* dst = (float4*)(out + E * N);
        int base = b * 1024 + threadIdx.x;
#pragma unroll
        for (int q = 0; q < 4; q++) dst[base + q * 256] = edge4[base + q * 256];
        return;
    }
    __shared__ float s_w1[E * E], s_b1[E], s_w2[E];
    __shared__ float s_b2;
    __shared__ float s_Vv[9];
    int t = threadIdx.x;
    for (int i = t; i < E * E; i += blockDim.x) s_w1[i] = vw1[i];
    if (t < E) { s_b1[t] = vb1[t]; s_w2[t] = vw2[t]; }
    if (t == 0) s_b2 = vb2[0];
    if (t < 9) s_Vv[t] = g_Vv[t];
    __syncthreads();
    int n = blockIdx.x * 256 + t;
    float hm[E];
#pragma unroll
    for (int k = 0; k < E; k++) {
        float s = 0.f;
#pragma unroll
        for (int o = 0; o < NF; o++) s += g_h[(o * N + n) * E + k];
        hm[k] = s * 0.125f;
        out[n * E + k] = hm[k];
    }
    float u[E];
#pragma unroll
    for (int k = 0; k < E; k++) {
        float s = s_b1[k];
#pragma unroll
        for (int l = 0; l < E; l++) s = fmaf(fmaxf(hm[l], 0.f), s_w1[l * E + k], s);
        u[k] = fmaxf(s, 0.f);
    }
    float coef = s_b2;
#pragma unroll
    for (int l = 0; l < E; l++) coef = fmaf(u[l], s_w2[l], coef);
    float Sx[3] = {0.f, 0.f, 0.f}, Sv[3] = {0.f, 0.f, 0.f};
#pragma unroll
    for (int o = 0; o < NF; o++) {
#pragma unroll
        for (int jj = 0; jj < 3; jj++) {
            float sgn = ((o >> (2 - jj)) & 1) ? -1.f : 1.f;
            Sx[jj] += sgn * g_so[(o * N + n) * 6 + jj];
            Sv[jj] += sgn * g_so[(o * N + n) * 6 + 3 + jj];
        }
    }
#pragma unroll
    for (int i = 0; i < 3; i++) {
        float dx = 0.125f * (s_Vv[i * 3 + 0] * Sx[0] + s_Vv[i * 3 + 1] * Sx[1] + s_Vv[i * 3 + 2] * Sx[2]);
        float dv = 0.125f * (s_Vv[i * 3 + 0] * Sv[0] + s_Vv[i * 3 + 1] * Sv[1] + s_Vv[i * 3 + 2] * Sv[2]);
        float vo = v[n * 3 + i] + dv;
        float xo = fmaf(vo, coef, x[n * 3 + i] + dx);
        out[E * N + N * N + n * 3 + i] = xo;
        out[E * N + N * N + 3 * N + n * 3 + i] = vo;
    }
}

extern "C" void kernel_launch(void* const* d_in, const int* in_sizes, int n_in,
                              void* d_out, int out_size) {
    const float* node_feat = (const float*)d_in[0];
    const float* edge = (const float*)d_in[1];
    const float* x = (const float*)d_in[2];
    const float* v = (const float*)d_in[3];
    const float* e0w1 = (const float*)d_in[4];
    const float* e0b1 = (const float*)d_in[5];
    const float* e0w2 = (const float*)d_in[6];
    const float* e0b2 = (const float*)d_in[7];
    const float* n0w1 = (const float*)d_in[8];
    const float* n0b1 = (const float*)d_in[9];
    const float* n0w2 = (const float*)d_in[10];
    const float* n0b2 = (const float*)d_in[11];
    const float* e1w1 = (const float*)d_in[12];
    const float* e1b1 = (const float*)d_in[13];
    const float* e1w2 = (const float*)d_in[14];
    const float* e1b2 = (const float*)d_in[15];
    const float* n1w1 = (const float*)d_in[16];
    const float* n1b1 = (const float*)d_in[17];
    const float* n1w2 = (const float*)d_in[18];
    const float* n1b2 = (const float*)d_in[19];
    const float* dw1 = (const float*)d_in[20];
    const float* db1 = (const float*)d_in[21];
    const float* dw2 = (const float*)d_in[22];
    const float* db2 = (const float*)d_in[23];
    const float* vcw1 = (const float*)d_in[24];
    const float* vcb1 = (const float*)d_in[25];
    const float* vcw2 = (const float*)d_in[26];
    const float* vcb2 = (const float*)d_in[27];
    float* out = (float*)d_out;

    float* pjT; cudaGetSymbolAddress((void**)&pjT, g_pjT);
    float* pic; cudaGetSymbolAddress((void**)&pic, g_pic);

    const int dyn = 2 * E * MS2 * (int)sizeof(float);   // 66560 B
    cudaFuncSetAttribute(k_pair, cudaFuncAttributeMaxDynamicSharedMemorySize, dyn);

    k_setup<<<1, 512>>>(x);
    k_embed<<<NF * N / 8, 256>>>(x, v, node_feat, e0w1, e0b1);
    k_pair<<<dim3(N / 4, NF), 256, dyn>>>(edge, e0w1, e0w2, e0b2, pjT, pic);
    k_node0<<<NF * N / 8, 256>>>(n0w1, n0b1, n0w2, n0b2, e1w1, e1b1);
    k_pair<<<dim3(N / 4, NF), 256, dyn>>>(edge, e1w1, e1w2, e1b2, pjT, pic);
    k_node1<<<NF * N / 8, 256>>>(n1w1, n1b1, n1w2, n1b2, dw1, db1, dw2, db2);
    k_final<<<66, 256>>>(x, v, vcw1, vcb1, vcw2, vcb2, (const float4*)edge, out);
}